// round 1
// baseline (speedup 1.0000x reference)
#include <cuda_runtime.h>
#include <cuda_bf16.h>

// ---------------------------------------------------------------------------
// Simplex4Net: B=32, N=64, D=64
// Strategy:
//   kA: keys/queries = pc @ W + b         (4 x [64x64] per batch)
//   kB: six pairwise Gram matrices * (scale*0.5)   -> g_E[6][B][64*64]
//   kC: main B*N^4 loop, packed f32x2, tanh-gate, per-(b,i) deterministic sum
//   kD: mean + gelu MLP head
// ---------------------------------------------------------------------------

#define BSZ 32
#define NP  64
#define DD  64

__device__ float g_K[4][BSZ][NP * DD];     // 0=Q, 1=K1, 2=K2, 3=K3
__device__ float g_E[6][BSZ][NP * NP];     // 0:(i,j) 1:(i,k) 2:(i,l) 3:(j,k) 4:(j,l) 5:(l,k)
__device__ float g_anchor[BSZ * NP];       // per (b,i) partial sums

// ----- f32x2 packed helpers (sm_100/103 PTX) -------------------------------
typedef unsigned long long ull;

__device__ __forceinline__ ull pk2(float lo, float hi) {
    ull r; asm("mov.b64 %0, {%1, %2};" : "=l"(r) : "f"(lo), "f"(hi)); return r;
}
__device__ __forceinline__ void upk2(ull v, float& lo, float& hi) {
    asm("mov.b64 {%0, %1}, %2;" : "=f"(lo), "=f"(hi) : "l"(v));
}
__device__ __forceinline__ ull add2(ull a, ull b) {
    ull r; asm("add.rn.f32x2 %0, %1, %2;" : "=l"(r) : "l"(a), "l"(b)); return r;
}
__device__ __forceinline__ ull mul2(ull a, ull b) {
    ull r; asm("mul.rn.f32x2 %0, %1, %2;" : "=l"(r) : "l"(a), "l"(b)); return r;
}
__device__ __forceinline__ ull fma2(ull a, ull b, ull c) {
    ull r; asm("fma.rn.f32x2 %0, %1, %2, %3;" : "=l"(r) : "l"(a), "l"(b), "l"(c)); return r;
}
__device__ __forceinline__ float tanhax(float x) {
    float y; asm("tanh.approx.f32 %0, %1;" : "=f"(y) : "f"(x)); return y;
}

// ---------------------------------------------------------------------------
// Kernel A: linear projections. grid=32 (one block per batch), 256 threads.
// ---------------------------------------------------------------------------
__global__ void kA(const float* __restrict__ pc,
                   const float* __restrict__ Wq,  const float* __restrict__ bq,
                   const float* __restrict__ Wk1, const float* __restrict__ bk1,
                   const float* __restrict__ Wk2, const float* __restrict__ bk2,
                   const float* __restrict__ Wk3, const float* __restrict__ bk3)
{
    int b = blockIdx.x;
    __shared__ float sp[NP * 3];
    __shared__ float sW[4][3 * DD];
    __shared__ float sb[4][DD];
    int t = threadIdx.x;
    if (t < 192) {
        sp[t]    = pc[b * 192 + t];
        sW[0][t] = Wq[t];
        sW[1][t] = Wk1[t];
        sW[2][t] = Wk2[t];
        sW[3][t] = Wk3[t];
    }
    if (t < 64) {
        sb[0][t] = bq[t]; sb[1][t] = bk1[t]; sb[2][t] = bk2[t]; sb[3][t] = bk3[t];
    }
    __syncthreads();
    for (int m = 0; m < 4; m++) {
        const float* W = sW[m];
        const float* bb = sb[m];
        for (int idx = t; idx < NP * DD; idx += 256) {
            int n = idx >> 6, d = idx & 63;
            float v = bb[d]
                    + sp[n * 3 + 0] * W[d]
                    + sp[n * 3 + 1] * W[64 + d]
                    + sp[n * 3 + 2] * W[128 + d];
            g_K[m][b][idx] = v;
        }
    }
}

// ---------------------------------------------------------------------------
// Kernel B: six Gram matrices, pre-scaled by 0.5 * rsqrt(64) = 0.0625.
// grid = (6, 32), 256 threads. E5 is stored transposed [l][k] for coalesced
// consumption in kC (lanes carry consecutive k there).
// ---------------------------------------------------------------------------
__global__ void kB()
{
    int p = blockIdx.x, b = blockIdx.y;
    const int XI[6] = {0, 0, 0, 1, 1, 3};   // E5 uses X=K3 (rows -> l)
    const int YI[6] = {1, 2, 3, 2, 3, 2};   //          Y=K2 (cols -> k)
    __shared__ float sX[NP][65];
    __shared__ float sY[NP][65];
    int t = threadIdx.x;
    const float* X = g_K[XI[p]][b];
    const float* Y = g_K[YI[p]][b];
    for (int idx = t; idx < NP * DD; idx += 256) {
        sX[idx >> 6][idx & 63] = X[idx];
        sY[idx >> 6][idx & 63] = Y[idx];
    }
    __syncthreads();
    for (int idx = t; idx < NP * NP; idx += 256) {
        int n = idx >> 6, m = idx & 63;
        float s = 0.f;
        #pragma unroll
        for (int d = 0; d < DD; d++)
            s = fmaf(sX[n][d], sY[m][d], s);
        g_E[p][b][idx] = s * 0.0625f;
    }
}

// ---------------------------------------------------------------------------
// Kernel C: main loop. grid = (i=64, b=32), 256 threads.
// Thread handles (k, l-pair); inner loop over j with f32x2 packing over l.
// ---------------------------------------------------------------------------
__global__ void __launch_bounds__(256) kC(const float* __restrict__ pc)
{
    __shared__ float SA[NP * NP];           // [j][k] = E3 + E0 row(i)
    __shared__ float SB[NP * NP];           // [j][l] = E4
    __shared__ ulonglong2 dXY[NP];          // per j: {x,x},{y,y}
    __shared__ ull        dZ[NP];           // per j: {z,z}
    __shared__ float4     dS[NP];           // scalar disp for cross products
    __shared__ float ek[NP], el[NP];
    __shared__ float red[256];

    int i = blockIdx.x, b = blockIdx.y, t = threadIdx.x;

    const float* E0r = &g_E[0][b][i * 64];
    const float* E3b = g_E[3][b];
    const float* E4b = g_E[4][b];
    for (int idx = t; idx < NP * NP; idx += 256) {
        SA[idx] = E3b[idx] + E0r[idx >> 6];
        SB[idx] = E4b[idx];
    }
    if (t < 64) {
        ek[t] = g_E[1][b][i * 64 + t];
        el[t] = g_E[2][b][i * 64 + t];
        float ix = pc[b * 192 + i * 3 + 0];
        float iy = pc[b * 192 + i * 3 + 1];
        float iz = pc[b * 192 + i * 3 + 2];
        float dx = pc[b * 192 + t * 3 + 0] - ix;
        float dy = pc[b * 192 + t * 3 + 1] - iy;
        float dz = pc[b * 192 + t * 3 + 2] - iz;
        dS[t] = make_float4(dx, dy, dz, 0.f);
        ulonglong2 v; v.x = pk2(dx, dx); v.y = pk2(dy, dy);
        dXY[t] = v;
        dZ[t] = pk2(dz, dz);
    }
    __syncthreads();

    const float* E5b = g_E[5][b];           // [l][k]
    const ull H05 = pk2(0.5f, 0.5f);
    ull acc = pk2(0.f, 0.f);

    for (int u = 0; u < 8; u++) {
        int p  = u * 256 + t;
        int k  = p & 63;
        int lp = p >> 6;                    // 0..31 across units
        int l0 = lp * 2, l1 = l0 + 1;

        float4 dk = dS[k], d0 = dS[l0], d1 = dS[l1];
        // cross(dk, dl) for both l's, packed per component
        float c0x = dk.y * d0.z - dk.z * d0.y;
        float c0y = dk.z * d0.x - dk.x * d0.z;
        float c0z = dk.x * d0.y - dk.y * d0.x;
        float c1x = dk.y * d1.z - dk.z * d1.y;
        float c1y = dk.z * d1.x - dk.x * d1.z;
        float c1z = dk.x * d1.y - dk.y * d1.x;
        ull cx2 = pk2(c0x, c1x);
        ull cy2 = pk2(c0y, c1y);
        ull cz2 = pk2(c0z, c1z);

        float ekk = ek[k];
        float e0 = E5b[l0 * 64 + k] + ekk + el[l0];
        float e1 = E5b[l1 * 64 + k] + ekk + el[l1];
        ull ec2 = pk2(e0, e1);

        const float* SAk = SA + k;
        const ull* SBl = reinterpret_cast<const ull*>(SB) + lp;

        #pragma unroll 8
        for (int j = 0; j < 64; j++) {
            float a  = SAk[j * 64];                 // LDS.32, conflict-free
            ull  b2  = SBl[j * 32];                 // LDS.64, warp broadcast
            ulonglong2 dj = dXY[j];                 // LDS.128 broadcast
            ull  dz2 = dZ[j];                       // LDS.64 broadcast

            ull a2 = pk2(a, a);
            ull e2 = add2(add2(a2, b2), ec2);
            ull det = fma2(cx2, dj.x, fma2(cy2, dj.y, mul2(cz2, dz2)));
            ull dd  = mul2(det, det);
            float elo, ehi; upk2(e2, elo, ehi);
            float th0 = tanhax(elo);
            float th1 = tanhax(ehi);
            ull th2 = pk2(th0, th1);
            ull g2  = fma2(th2, H05, H05);          // sigmoid = 0.5*tanh + 0.5
            acc = fma2(dd, g2, acc);
        }
    }

    float alo, ahi; upk2(acc, alo, ahi);
    red[t] = alo + ahi;
    __syncthreads();
    for (int s = 128; s > 0; s >>= 1) {
        if (t < s) red[t] += red[t + s];
        __syncthreads();
    }
    if (t == 0) g_anchor[b * 64 + i] = red[0];
}

// ---------------------------------------------------------------------------
// Kernel D: pooled mean + gelu(tanh-approx) MLP head. 1 block, 32 threads.
// ---------------------------------------------------------------------------
__global__ void kD(const float* __restrict__ W1, const float* __restrict__ b1,
                   const float* __restrict__ W2, const float* __restrict__ b2,
                   float* __restrict__ out)
{
    int b = threadIdx.x;
    if (b >= BSZ) return;
    float s = 0.f;
    for (int i = 0; i < NP; i++) s += g_anchor[b * 64 + i];
    s *= (1.0f / 16777216.0f);              // / N^3 (agg) / N (mean over anchors)
    float o = b2[0];
    for (int j = 0; j < 32; j++) {
        float x = s * W1[j] + b1[j];
        float u = 0.7978845608028654f * (x + 0.044715f * x * x * x);
        float h = 0.5f * x * (1.0f + tanhf(u));
        o += h * W2[j];
    }
    out[b] = o;
}

// ---------------------------------------------------------------------------
extern "C" void kernel_launch(void* const* d_in, const int* in_sizes, int n_in,
                              void* d_out, int out_size)
{
    const float* pc  = (const float*)d_in[0];
    const float* Wq  = (const float*)d_in[1];
    const float* bq  = (const float*)d_in[2];
    const float* Wk1 = (const float*)d_in[3];
    const float* bk1 = (const float*)d_in[4];
    const float* Wk2 = (const float*)d_in[5];
    const float* bk2 = (const float*)d_in[6];
    const float* Wk3 = (const float*)d_in[7];
    const float* bk3 = (const float*)d_in[8];
    const float* W1  = (const float*)d_in[9];
    const float* b1  = (const float*)d_in[10];
    const float* W2  = (const float*)d_in[11];
    const float* b2  = (const float*)d_in[12];
    float* out = (float*)d_out;

    kA<<<BSZ, 256>>>(pc, Wq, bq, Wk1, bk1, Wk2, bk2, Wk3, bk3);
    kB<<<dim3(6, BSZ), 256>>>();
    kC<<<dim3(NP, BSZ), 256>>>(pc);
    kD<<<1, 32>>>(W1, b1, W2, b2, out);
}

// round 2
// speedup vs baseline: 1.0661x; 1.0661x over previous
#include <cuda_runtime.h>
#include <cuda_bf16.h>

// ---------------------------------------------------------------------------
// Simplex4Net: B=32, N=64, D=64
//   kA: projections Q,K1,K2,K3
//   kB: six pairwise Gram matrices * 0.0625 (= 0.5*rsqrt(64))
//   kC: main B*N^4 loop, f32x2 packed over l, j unrolled x2 via packed-pair
//       shared layouts; one tanh per element (sigmoid = 0.5+0.5*tanh(e/2))
//   kD: mean + gelu MLP head (parallel)
// ---------------------------------------------------------------------------

#define BSZ 32
#define NP  64
#define DD  64

__device__ float g_K[4][BSZ][NP * DD];     // 0=Q, 1=K1, 2=K2, 3=K3
__device__ float g_E[6][BSZ][NP * NP];     // 0:(i,j) 1:(i,k) 2:(i,l) 3:(j,k) 4:(j,l) 5:(l,k) [transposed]
__device__ float g_anchor[BSZ * NP];       // per (b,i) partial sums

typedef unsigned long long ull;

__device__ __forceinline__ ull pk2(float lo, float hi) {
    ull r; asm("mov.b64 %0, {%1, %2};" : "=l"(r) : "f"(lo), "f"(hi)); return r;
}
__device__ __forceinline__ void upk2(ull v, float& lo, float& hi) {
    asm("mov.b64 {%0, %1}, %2;" : "=f"(lo), "=f"(hi) : "l"(v));
}
__device__ __forceinline__ ull add2(ull a, ull b) {
    ull r; asm("add.rn.f32x2 %0, %1, %2;" : "=l"(r) : "l"(a), "l"(b)); return r;
}
__device__ __forceinline__ ull mul2(ull a, ull b) {
    ull r; asm("mul.rn.f32x2 %0, %1, %2;" : "=l"(r) : "l"(a), "l"(b)); return r;
}
__device__ __forceinline__ ull fma2(ull a, ull b, ull c) {
    ull r; asm("fma.rn.f32x2 %0, %1, %2, %3;" : "=l"(r) : "l"(a), "l"(b), "l"(c)); return r;
}
__device__ __forceinline__ float tanhax(float x) {
    float y; asm("tanh.approx.f32 %0, %1;" : "=f"(y) : "f"(x)); return y;
}

// ---------------------------------------------------------------------------
// Kernel A: linear projections. grid=32, 256 threads.
// ---------------------------------------------------------------------------
__global__ void kA(const float* __restrict__ pc,
                   const float* __restrict__ Wq,  const float* __restrict__ bq,
                   const float* __restrict__ Wk1, const float* __restrict__ bk1,
                   const float* __restrict__ Wk2, const float* __restrict__ bk2,
                   const float* __restrict__ Wk3, const float* __restrict__ bk3)
{
    int b = blockIdx.x;
    __shared__ float sp[NP * 3];
    __shared__ float sW[4][3 * DD];
    __shared__ float sb[4][DD];
    int t = threadIdx.x;
    if (t < 192) {
        sp[t]    = pc[b * 192 + t];
        sW[0][t] = Wq[t];
        sW[1][t] = Wk1[t];
        sW[2][t] = Wk2[t];
        sW[3][t] = Wk3[t];
    }
    if (t < 64) {
        sb[0][t] = bq[t]; sb[1][t] = bk1[t]; sb[2][t] = bk2[t]; sb[3][t] = bk3[t];
    }
    __syncthreads();
    for (int m = 0; m < 4; m++) {
        const float* W = sW[m];
        const float* bb = sb[m];
        for (int idx = t; idx < NP * DD; idx += 256) {
            int n = idx >> 6, d = idx & 63;
            float v = bb[d]
                    + sp[n * 3 + 0] * W[d]
                    + sp[n * 3 + 1] * W[64 + d]
                    + sp[n * 3 + 2] * W[128 + d];
            g_K[m][b][idx] = v;
        }
    }
}

// ---------------------------------------------------------------------------
// Kernel B: six Gram matrices pre-scaled by 0.0625. grid=(6,32), 256 thr.
// E5 stored transposed [l][k].
// ---------------------------------------------------------------------------
__global__ void kB()
{
    int p = blockIdx.x, b = blockIdx.y;
    const int XI[6] = {0, 0, 0, 1, 1, 3};
    const int YI[6] = {1, 2, 3, 2, 3, 2};
    __shared__ float sX[NP][65];
    __shared__ float sY[NP][65];
    int t = threadIdx.x;
    const float* X = g_K[XI[p]][b];
    const float* Y = g_K[YI[p]][b];
    for (int idx = t; idx < NP * DD; idx += 256) {
        sX[idx >> 6][idx & 63] = X[idx];
        sY[idx >> 6][idx & 63] = Y[idx];
    }
    __syncthreads();
    for (int idx = t; idx < NP * NP; idx += 256) {
        int n = idx >> 6, m = idx & 63;
        float s = 0.f;
        #pragma unroll
        for (int d = 0; d < DD; d++)
            s = fmaf(sX[n][d], sY[m][d], s);
        g_E[p][b][idx] = s * 0.0625f;
    }
}

// ---------------------------------------------------------------------------
// Kernel C: main loop. grid=(i=64,b=32), 256 threads.
// Thread handles (k, l-pair); inner loop over jp (2 j's per iter).
//
// Shared layouts (per block, i fixed):
//  SAP[jp][k]   (ull)        = { E3[2jp][k]+E0[i][2jp],  E3[2jp+1][k]+E0[i][2jp+1] }
//  SBP[jp][lp]  (ulonglong2) = { {B[2jp][l0],B[2jp][l1]}, {B[2jp+1][l0],B[2jp+1][l1]} }
//                              where B[j][l] = E4[j][l] + E2[i][l]
//  DJ[jp][6]    (ull)        = {x,x},{y,y},{z,z} for j=2jp then j=2jp+1
// Per-thread constants per unit: ec2 = { E1[i][k]+E5[l0][k], E1[i][k]+E5[l1][k] },
// packed cross products cx2, cy2, cz2 of (disp_k x disp_l0 / l1).
// ---------------------------------------------------------------------------
__global__ void __launch_bounds__(256) kC(const float* __restrict__ pc)
{
    __shared__ ull        SAP[32 * 64];     // 16 KB
    __shared__ ulonglong2 SBP[32 * 32];     // 16 KB
    __shared__ ull        DJ[32][6];        // 1.5 KB
    __shared__ float4     dS[NP];
    __shared__ float      ekA[NP];
    __shared__ float      red[256];

    int i = blockIdx.x, b = blockIdx.y, t = threadIdx.x;

    const float* E0r = &g_E[0][b][i * 64];
    const float* E2r = &g_E[2][b][i * 64];
    const float* E3b = g_E[3][b];
    const float* E4b = g_E[4][b];

    float* SAPf = reinterpret_cast<float*>(SAP);
    float* SBPf = reinterpret_cast<float*>(SBP);

    for (int idx = t; idx < NP * NP; idx += 256) {
        int j = idx >> 6, c = idx & 63;          // c = k for SAP, l for SBP
        float av = E3b[idx] + E0r[j];
        SAPf[((j >> 1) << 7) + (c << 1) + (j & 1)] = av;
        float bv = E4b[idx] + E2r[c];
        SBPf[((j >> 1) << 7) + ((c >> 1) << 2) + ((j & 1) << 1) + (c & 1)] = bv;
    }
    if (t < 64) {
        ekA[t] = g_E[1][b][i * 64 + t];
        float ix = pc[b * 192 + i * 3 + 0];
        float iy = pc[b * 192 + i * 3 + 1];
        float iz = pc[b * 192 + i * 3 + 2];
        float dx = pc[b * 192 + t * 3 + 0] - ix;
        float dy = pc[b * 192 + t * 3 + 1] - iy;
        float dz = pc[b * 192 + t * 3 + 2] - iz;
        dS[t] = make_float4(dx, dy, dz, 0.f);
    }
    __syncthreads();
    if (t < 32) {
        float4 d0 = dS[2 * t], d1 = dS[2 * t + 1];
        DJ[t][0] = pk2(d0.x, d0.x);
        DJ[t][1] = pk2(d0.y, d0.y);
        DJ[t][2] = pk2(d0.z, d0.z);
        DJ[t][3] = pk2(d1.x, d1.x);
        DJ[t][4] = pk2(d1.y, d1.y);
        DJ[t][5] = pk2(d1.z, d1.z);
    }
    __syncthreads();

    const float* E5b = g_E[5][b];               // [l][k]
    const ull H05 = pk2(0.5f, 0.5f);
    ull acc = pk2(0.f, 0.f);

    for (int u = 0; u < 8; u++) {
        int p  = u * 256 + t;
        int k  = p & 63;
        int lp = p >> 6;                        // 0..31 across units
        int l0 = lp * 2, l1 = l0 + 1;

        float4 dk = dS[k], d0 = dS[l0], d1 = dS[l1];
        float c0x = dk.y * d0.z - dk.z * d0.y;
        float c0y = dk.z * d0.x - dk.x * d0.z;
        float c0z = dk.x * d0.y - dk.y * d0.x;
        float c1x = dk.y * d1.z - dk.z * d1.y;
        float c1y = dk.z * d1.x - dk.x * d1.z;
        float c1z = dk.x * d1.y - dk.y * d1.x;
        ull cx2 = pk2(c0x, c1x);
        ull cy2 = pk2(c0y, c1y);
        ull cz2 = pk2(c0z, c1z);

        float ekk = ekA[k];
        float e5a = E5b[l0 * 64 + k];            // LDG, L2-resident, per-unit
        float e5b_ = E5b[l1 * 64 + k];
        ull ec2 = pk2(ekk + e5a, ekk + e5b_);

        const ull* SAPk        = SAP + k;
        const ulonglong2* SBPl = SBP + lp;

        #pragma unroll 8
        for (int jp = 0; jp < 32; jp++) {
            ull apair       = SAPk[jp << 6];     // LDS.64 {a(j0),a(j1)}
            ulonglong2 bp   = SBPl[jp << 5];     // LDS.128 broadcast
            ulonglong2 dxy0 = *reinterpret_cast<const ulonglong2*>(&DJ[jp][0]); // {x0,y0}
            ulonglong2 dzx1 = *reinterpret_cast<const ulonglong2*>(&DJ[jp][2]); // {z0,x1}
            ulonglong2 dyz1 = *reinterpret_cast<const ulonglong2*>(&DJ[jp][4]); // {y1,z1}

            float a0, a1; upk2(apair, a0, a1);

            // j0
            {
                ull a2  = pk2(a0, a0);
                ull e2  = add2(add2(a2, bp.x), ec2);
                ull det = fma2(cx2, dxy0.x, fma2(cy2, dxy0.y, mul2(cz2, dzx1.x)));
                ull dd  = mul2(det, det);
                float elo, ehi; upk2(e2, elo, ehi);
                ull th2 = pk2(tanhax(elo), tanhax(ehi));
                ull g2  = fma2(th2, H05, H05);
                acc = fma2(dd, g2, acc);
            }
            // j1
            {
                ull a2  = pk2(a1, a1);
                ull e2  = add2(add2(a2, bp.y), ec2);
                ull det = fma2(cx2, dzx1.y, fma2(cy2, dyz1.x, mul2(cz2, dyz1.y)));
                ull dd  = mul2(det, det);
                float elo, ehi; upk2(e2, elo, ehi);
                ull th2 = pk2(tanhax(elo), tanhax(ehi));
                ull g2  = fma2(th2, H05, H05);
                acc = fma2(dd, g2, acc);
            }
        }
    }

    float alo, ahi; upk2(acc, alo, ahi);
    red[t] = alo + ahi;
    __syncthreads();
    for (int s = 128; s > 0; s >>= 1) {
        if (t < s) red[t] += red[t + s];
        __syncthreads();
    }
    if (t == 0) g_anchor[b * 64 + i] = red[0];
}

// ---------------------------------------------------------------------------
// Kernel D: pooled mean + gelu MLP head. grid=32, 64 threads.
// ---------------------------------------------------------------------------
__global__ void kD(const float* __restrict__ W1, const float* __restrict__ b1,
                   const float* __restrict__ W2, const float* __restrict__ b2,
                   float* __restrict__ out)
{
    int b = blockIdx.x, t = threadIdx.x;
    __shared__ float sred[2];
    float v = g_anchor[b * 64 + t];
    #pragma unroll
    for (int off = 16; off > 0; off >>= 1)
        v += __shfl_xor_sync(0xFFFFFFFFu, v, off);
    if ((t & 31) == 0) sred[t >> 5] = v;
    __syncthreads();
    if (t < 32) {
        float s = (sred[0] + sred[1]) * (1.0f / 16777216.0f);  // /N^3 /N
        float x = s * W1[t] + b1[t];
        float u = 0.7978845608028654f * (x + 0.044715f * x * x * x);
        float h = 0.5f * x * (1.0f + tanhf(u));
        float c = h * W2[t];
        #pragma unroll
        for (int off = 16; off > 0; off >>= 1)
            c += __shfl_xor_sync(0xFFFFFFFFu, c, off);
        if (t == 0) out[b] = c + b2[0];
    }
}

// ---------------------------------------------------------------------------
extern "C" void kernel_launch(void* const* d_in, const int* in_sizes, int n_in,
                              void* d_out, int out_size)
{
    const float* pc  = (const float*)d_in[0];
    const float* Wq  = (const float*)d_in[1];
    const float* bq  = (const float*)d_in[2];
    const float* Wk1 = (const float*)d_in[3];
    const float* bk1 = (const float*)d_in[4];
    const float* Wk2 = (const float*)d_in[5];
    const float* bk2 = (const float*)d_in[6];
    const float* Wk3 = (const float*)d_in[7];
    const float* bk3 = (const float*)d_in[8];
    const float* W1  = (const float*)d_in[9];
    const float* b1  = (const float*)d_in[10];
    const float* W2  = (const float*)d_in[11];
    const float* b2  = (const float*)d_in[12];
    float* out = (float*)d_out;

    kA<<<BSZ, 256>>>(pc, Wq, bq, Wk1, bk1, Wk2, bk2, Wk3, bk3);
    kB<<<dim3(6, BSZ), 256>>>();
    kC<<<dim3(NP, BSZ), 256>>>(pc);
    kD<<<BSZ, 64>>>(W1, b1, W2, b2, out);
}

// round 3
// speedup vs baseline: 1.1016x; 1.0333x over previous
#include <cuda_runtime.h>
#include <cuda_bf16.h>

// ---------------------------------------------------------------------------
// Simplex4Net: B=32, N=64, D=64
//   kA: projections Q,K1,K2,K3
//   kB: six pairwise Gram matrices * 0.0625
//   kC: main B*N^4 loop; thread = (k, l-quad), 2x f32x2 streams, j unrolled x2
//   kD: mean + gelu MLP head
// ---------------------------------------------------------------------------

#define BSZ 32
#define NP  64
#define DD  64

__device__ float g_K[4][BSZ][NP * DD];
__device__ float g_E[6][BSZ][NP * NP];   // 0:(i,j) 1:(i,k) 2:(i,l) 3:(j,k) 4:(j,l) 5:(l,k)^T
__device__ float g_anchor[BSZ * NP];

typedef unsigned long long ull;

__device__ __forceinline__ ull pk2(float lo, float hi) {
    ull r; asm("mov.b64 %0, {%1, %2};" : "=l"(r) : "f"(lo), "f"(hi)); return r;
}
__device__ __forceinline__ void upk2(ull v, float& lo, float& hi) {
    asm("mov.b64 {%0, %1}, %2;" : "=f"(lo), "=f"(hi) : "l"(v));
}
__device__ __forceinline__ ull add2(ull a, ull b) {
    ull r; asm("add.rn.f32x2 %0, %1, %2;" : "=l"(r) : "l"(a), "l"(b)); return r;
}
__device__ __forceinline__ ull mul2(ull a, ull b) {
    ull r; asm("mul.rn.f32x2 %0, %1, %2;" : "=l"(r) : "l"(a), "l"(b)); return r;
}
__device__ __forceinline__ ull fma2(ull a, ull b, ull c) {
    ull r; asm("fma.rn.f32x2 %0, %1, %2, %3;" : "=l"(r) : "l"(a), "l"(b), "l"(c)); return r;
}
__device__ __forceinline__ float tanhax(float x) {
    float y; asm("tanh.approx.f32 %0, %1;" : "=f"(y) : "f"(x)); return y;
}

// ---------------------------------------------------------------------------
__global__ void kA(const float* __restrict__ pc,
                   const float* __restrict__ Wq,  const float* __restrict__ bq,
                   const float* __restrict__ Wk1, const float* __restrict__ bk1,
                   const float* __restrict__ Wk2, const float* __restrict__ bk2,
                   const float* __restrict__ Wk3, const float* __restrict__ bk3)
{
    int b = blockIdx.x;
    __shared__ float sp[NP * 3];
    __shared__ float sW[4][3 * DD];
    __shared__ float sb[4][DD];
    int t = threadIdx.x;
    if (t < 192) {
        sp[t]    = pc[b * 192 + t];
        sW[0][t] = Wq[t];
        sW[1][t] = Wk1[t];
        sW[2][t] = Wk2[t];
        sW[3][t] = Wk3[t];
    }
    if (t < 64) {
        sb[0][t] = bq[t]; sb[1][t] = bk1[t]; sb[2][t] = bk2[t]; sb[3][t] = bk3[t];
    }
    __syncthreads();
    for (int m = 0; m < 4; m++) {
        const float* W = sW[m];
        const float* bb = sb[m];
        for (int idx = t; idx < NP * DD; idx += 256) {
            int n = idx >> 6, d = idx & 63;
            float v = bb[d]
                    + sp[n * 3 + 0] * W[d]
                    + sp[n * 3 + 1] * W[64 + d]
                    + sp[n * 3 + 2] * W[128 + d];
            g_K[m][b][idx] = v;
        }
    }
}

// ---------------------------------------------------------------------------
__global__ void kB()
{
    int p = blockIdx.x, b = blockIdx.y;
    const int XI[6] = {0, 0, 0, 1, 1, 3};
    const int YI[6] = {1, 2, 3, 2, 3, 2};
    __shared__ float sX[NP][65];
    __shared__ float sY[NP][65];
    int t = threadIdx.x;
    const float* X = g_K[XI[p]][b];
    const float* Y = g_K[YI[p]][b];
    for (int idx = t; idx < NP * DD; idx += 256) {
        sX[idx >> 6][idx & 63] = X[idx];
        sY[idx >> 6][idx & 63] = Y[idx];
    }
    __syncthreads();
    for (int idx = t; idx < NP * NP; idx += 256) {
        int n = idx >> 6, m = idx & 63;
        float s = 0.f;
        #pragma unroll
        for (int d = 0; d < DD; d++)
            s = fmaf(sX[n][d], sY[m][d], s);
        g_E[p][b][idx] = s * 0.0625f;
    }
}

// ---------------------------------------------------------------------------
// Kernel C: grid=(i=64,b=32), 256 threads. Thread = (k = t&63, l-quad).
// 4 units: lq = u*4 + (t>>6); l = 4lq .. 4lq+3. Inner loop jp (2 j's).
//
// SA2[j][k]  (ull)         = {a, a},  a = E3[j][k] + E0[i][j]
// SB4[j][lq] (ulonglong2)  = {{b(4lq),b(4lq+1)},{b(4lq+2),b(4lq+3)}},
//                            b(l) = E4[j][l] + E2[i][l]
// DJ[jp][6]  (ull)         = {x,x},{y,y},{z,z} for j=2jp, then j=2jp+1
// ---------------------------------------------------------------------------
__global__ void __launch_bounds__(256) kC(const float* __restrict__ pc)
{
    __shared__ ull        SA2[64 * 64];      // 32 KB
    __shared__ ulonglong2 SB4[64 * 16];      // 16 KB
    __shared__ ull        DJ[32][6];         // 1.5 KB
    __shared__ float4     dS[NP];
    __shared__ float      ekA[NP];
    __shared__ float      red[256];

    int i = blockIdx.x, b = blockIdx.y, t = threadIdx.x;

    const float* E0r = &g_E[0][b][i * 64];
    const float* E2r = &g_E[2][b][i * 64];
    const float* E3b = g_E[3][b];
    const float* E4b = g_E[4][b];

    float* SA2f = reinterpret_cast<float*>(SA2);
    float* SB4f = reinterpret_cast<float*>(SB4);

    for (int idx = t; idx < NP * NP; idx += 256) {
        int j = idx >> 6, c = idx & 63;
        float av = E3b[idx] + E0r[j];
        SA2f[(j << 7) + (c << 1) + 0] = av;
        SA2f[(j << 7) + (c << 1) + 1] = av;
        float bv = E4b[idx] + E2r[c];
        SB4f[(j << 6) + c] = bv;            // (j*16 + c>>2)*4 + (c&3) == j*64+c
    }
    if (t < 64) {
        ekA[t] = g_E[1][b][i * 64 + t];
        float ix = pc[b * 192 + i * 3 + 0];
        float iy = pc[b * 192 + i * 3 + 1];
        float iz = pc[b * 192 + i * 3 + 2];
        float dx = pc[b * 192 + t * 3 + 0] - ix;
        float dy = pc[b * 192 + t * 3 + 1] - iy;
        float dz = pc[b * 192 + t * 3 + 2] - iz;
        dS[t] = make_float4(dx, dy, dz, 0.f);
    }
    __syncthreads();
    if (t < 32) {
        float4 d0 = dS[2 * t], d1 = dS[2 * t + 1];
        DJ[t][0] = pk2(d0.x, d0.x);
        DJ[t][1] = pk2(d0.y, d0.y);
        DJ[t][2] = pk2(d0.z, d0.z);
        DJ[t][3] = pk2(d1.x, d1.x);
        DJ[t][4] = pk2(d1.y, d1.y);
        DJ[t][5] = pk2(d1.z, d1.z);
    }
    __syncthreads();

    const float* E5b = g_E[5][b];            // [l][k]
    const ull H05 = pk2(0.5f, 0.5f);
    ull accP = pk2(0.f, 0.f);
    ull accQ = pk2(0.f, 0.f);

    int k = t & 63;
    const ull* SA2k = SA2 + k;
    float ekk_cached = 0.f;                  // loaded per-unit below (k fixed)

    #pragma unroll 1
    for (int u = 0; u < 4; u++) {
        int lq = u * 4 + (t >> 6);
        int l0 = lq * 4;

        float4 dk = dS[k];
        float4 dA = dS[l0 + 0];
        float4 dB = dS[l0 + 1];
        float4 dC = dS[l0 + 2];
        float4 dD = dS[l0 + 3];

        // packed cross products for the 4 l's: (dk x dl)
        ull cx01 = pk2(dk.y * dA.z - dk.z * dA.y, dk.y * dB.z - dk.z * dB.y);
        ull cy01 = pk2(dk.z * dA.x - dk.x * dA.z, dk.z * dB.x - dk.x * dB.z);
        ull cz01 = pk2(dk.x * dA.y - dk.y * dA.x, dk.x * dB.y - dk.y * dB.x);
        ull cx23 = pk2(dk.y * dC.z - dk.z * dC.y, dk.y * dD.z - dk.z * dD.y);
        ull cy23 = pk2(dk.z * dC.x - dk.x * dC.z, dk.z * dD.x - dk.x * dD.z);
        ull cz23 = pk2(dk.x * dC.y - dk.y * dC.x, dk.x * dD.y - dk.y * dD.x);

        ekk_cached = ekA[k];
        float e5_0 = E5b[(l0 + 0) * 64 + k];
        float e5_1 = E5b[(l0 + 1) * 64 + k];
        float e5_2 = E5b[(l0 + 2) * 64 + k];
        float e5_3 = E5b[(l0 + 3) * 64 + k];
        ull ecA = pk2(ekk_cached + e5_0, ekk_cached + e5_1);
        ull ecB = pk2(ekk_cached + e5_2, ekk_cached + e5_3);

        const ulonglong2* SB4l = SB4 + lq;

        #pragma unroll 4
        for (int jp = 0; jp < 32; jp++) {
            ull a0r = SA2k[(2 * jp) << 6];                // LDS.64 {a,a}
            ull a1r = SA2k[(2 * jp + 1) << 6];
            ulonglong2 b0 = SB4l[(2 * jp) << 4];          // LDS.128 broadcast
            ulonglong2 b1 = SB4l[(2 * jp + 1) << 4];
            ulonglong2 dxy0 = *reinterpret_cast<const ulonglong2*>(&DJ[jp][0]);
            ulonglong2 dzx1 = *reinterpret_cast<const ulonglong2*>(&DJ[jp][2]);
            ulonglong2 dyz1 = *reinterpret_cast<const ulonglong2*>(&DJ[jp][4]);

            // ---- j0 = 2jp ----
            {
                ull eP = add2(add2(a0r, b0.x), ecA);
                ull eQ = add2(add2(a0r, b0.y), ecB);
                ull detP = fma2(cx01, dxy0.x, fma2(cy01, dxy0.y, mul2(cz01, dzx1.x)));
                ull detQ = fma2(cx23, dxy0.x, fma2(cy23, dxy0.y, mul2(cz23, dzx1.x)));
                ull ddP = mul2(detP, detP);
                ull ddQ = mul2(detQ, detQ);
                float p0, p1, q0, q1;
                upk2(eP, p0, p1); upk2(eQ, q0, q1);
                ull thP = pk2(tanhax(p0), tanhax(p1));
                ull thQ = pk2(tanhax(q0), tanhax(q1));
                ull gP = fma2(thP, H05, H05);
                ull gQ = fma2(thQ, H05, H05);
                accP = fma2(ddP, gP, accP);
                accQ = fma2(ddQ, gQ, accQ);
            }
            // ---- j1 = 2jp+1 ----
            {
                ull eP = add2(add2(a1r, b1.x), ecA);
                ull eQ = add2(add2(a1r, b1.y), ecB);
                ull detP = fma2(cx01, dzx1.y, fma2(cy01, dyz1.x, mul2(cz01, dyz1.y)));
                ull detQ = fma2(cx23, dzx1.y, fma2(cy23, dyz1.x, mul2(cz23, dyz1.y)));
                ull ddP = mul2(detP, detP);
                ull ddQ = mul2(detQ, detQ);
                float p0, p1, q0, q1;
                upk2(eP, p0, p1); upk2(eQ, q0, q1);
                ull thP = pk2(tanhax(p0), tanhax(p1));
                ull thQ = pk2(tanhax(q0), tanhax(q1));
                ull gP = fma2(thP, H05, H05);
                ull gQ = fma2(thQ, H05, H05);
                accP = fma2(ddP, gP, accP);
                accQ = fma2(ddQ, gQ, accQ);
            }
        }
    }

    float a0, a1, b0_, b1_;
    upk2(accP, a0, a1); upk2(accQ, b0_, b1_);
    red[t] = (a0 + a1) + (b0_ + b1_);
    __syncthreads();
    for (int s = 128; s > 0; s >>= 1) {
        if (t < s) red[t] += red[t + s];
        __syncthreads();
    }
    if (t == 0) g_anchor[b * 64 + i] = red[0];
}

// ---------------------------------------------------------------------------
__global__ void kD(const float* __restrict__ W1, const float* __restrict__ b1,
                   const float* __restrict__ W2, const float* __restrict__ b2,
                   float* __restrict__ out)
{
    int b = blockIdx.x, t = threadIdx.x;
    __shared__ float sred[2];
    float v = g_anchor[b * 64 + t];
    #pragma unroll
    for (int off = 16; off > 0; off >>= 1)
        v += __shfl_xor_sync(0xFFFFFFFFu, v, off);
    if ((t & 31) == 0) sred[t >> 5] = v;
    __syncthreads();
    if (t < 32) {
        float s = (sred[0] + sred[1]) * (1.0f / 16777216.0f);
        float x = s * W1[t] + b1[t];
        float u = 0.7978845608028654f * (x + 0.044715f * x * x * x);
        float h = 0.5f * x * (1.0f + tanhf(u));
        float c = h * W2[t];
        #pragma unroll
        for (int off = 16; off > 0; off >>= 1)
            c += __shfl_xor_sync(0xFFFFFFFFu, c, off);
        if (t == 0) out[b] = c + b2[0];
    }
}

// ---------------------------------------------------------------------------
extern "C" void kernel_launch(void* const* d_in, const int* in_sizes, int n_in,
                              void* d_out, int out_size)
{
    const float* pc  = (const float*)d_in[0];
    const float* Wq  = (const float*)d_in[1];
    const float* bq  = (const float*)d_in[2];
    const float* Wk1 = (const float*)d_in[3];
    const float* bk1 = (const float*)d_in[4];
    const float* Wk2 = (const float*)d_in[5];
    const float* bk2 = (const float*)d_in[6];
    const float* Wk3 = (const float*)d_in[7];
    const float* bk3 = (const float*)d_in[8];
    const float* W1  = (const float*)d_in[9];
    const float* b1  = (const float*)d_in[10];
    const float* W2  = (const float*)d_in[11];
    const float* b2  = (const float*)d_in[12];
    float* out = (float*)d_out;

    kA<<<BSZ, 256>>>(pc, Wq, bq, Wk1, bk1, Wk2, bk2, Wk3, bk3);
    kB<<<dim3(6, BSZ), 256>>>();
    kC<<<dim3(NP, BSZ), 256>>>(pc);
    kD<<<BSZ, 64>>>(W1, b1, W2, b2, out);
}